// round 8
// baseline (speedup 1.0000x reference)
#include <cuda_runtime.h>
#include <stdint.h>
#include <math.h>

#define BB 32
#define PP 196
#define EE 2048
#define AA 512
#define DD 512
#define MMM 512
#define VV 10000
#define LLL 20
#define TTT 19
#define KCC 3072
#define G4 2048    /* 4*D */
#define NBIG 12560 /* fbeta | dec_att(unused) | fc */

#define OFF_PRED  0
#define OFF_CAPS  (BB*TTT*VV)
#define OFF_ALPHA (OFF_CAPS + BB*LLL)
#define OFF_SORT  (OFF_ALPHA + BB*TTT*PP)

#define COL_GATE 0
#define COL_FC   2560

typedef unsigned long long ull;
typedef unsigned int u32;

// -------- scratch --------
__device__ float g_att1[BB*PP*AA];
__device__ float g_wcomb[KCC*G4 + 2048];   // [W_ih | W_hh] k-pair-interleaved
__device__ float g_wic[EE*1024 + 2048];    // [W_init_h | W_init_c]
__device__ float g_wbig[DD*NBIG + 4096];   // [W_fbeta | W_dec_att | W_fc]
__device__ float g_mean[BB*EE];
__device__ float g_h[BB*DD];
__device__ float g_c[BB*DD];
__device__ float g_alpha[BB*PP];
__device__ float g_x2[BB*2048];            // gate*awe
__device__ float g_part[24*BB*G4];
__device__ float g_part2[8*BB*NBIG];
__device__ int   g_sortind[BB];
__device__ int   g_declen[BB];
__device__ int   g_caps[BB*LLL];

__device__ __forceinline__ float sigm(float x) { return 1.0f / (1.0f + expf(-x)); }

__device__ __forceinline__ ull ffma2(ull a, ull b, ull c) {
    ull d;
    asm("fma.rn.f32x2 %0, %1, %2, %3;" : "=l"(d) : "l"(a), "l"(b), "l"(c));
    return d;
}
__device__ __forceinline__ float pairsum(ull v) {
    float2 f = *reinterpret_cast<float2*>(&v);
    return f.x + f.y;
}
__device__ __forceinline__ ull dup2(float a) {
    ull r;
    asm("mov.b64 %0, {%1, %1};" : "=l"(r) : "f"(a));
    return r;
}
__device__ __forceinline__ void cp_async16(u32 smem_addr, const void* gptr) {
    asm volatile("cp.async.cg.shared.global [%0], [%1], 16;" :: "r"(smem_addr), "l"(gptr));
}
__device__ __forceinline__ void cp_commit() {
    asm volatile("cp.async.commit_group;" ::: "memory");
}
template<int N> __device__ __forceinline__ void cp_wait() {
    asm volatile("cp.async.wait_group %0;" :: "n"(N) : "memory");
}

// ============ cp.async skinny-GEMM body, row-pointer X loader ================
// rowp[r] (smem, 32 entries) points at X row r's K-segment start.
// 256 thr: bg=tid>>6 (4 x 8 rows), cg=tid&63 -> cols j0, j0+64.
template<int KSEG>
__device__ __forceinline__ void gemm4r(
    float* Xs, float* Ws, const float* const* rowp,
    const float* __restrict__ Wp, int N2,
    float* __restrict__ part, int npad, int N,
    int chunk, int seg, int colOffset)
{
    int tid = threadIdx.x;
    int cg = tid & 63, bg = tid >> 6;
    int colbase = colOffset + chunk * 128;
    int kb = seg * KSEG;

    __syncthreads();   // rowp ready

    const int PER = (32 * KSEG / 4) / 256;
    #pragma unroll
    for (int i = 0; i < PER; ++i) {
        int f = i * 256 + tid;
        int r = f / (KSEG / 4);
        int c4 = (f % (KSEG / 4)) * 4;
        *reinterpret_cast<float4*>(&Xs[r * KSEG + c4]) =
            *reinterpret_cast<const float4*>(rowp[r] + c4);
    }

    const float* wsrc = Wp + (size_t)(kb >> 1) * N2 + (size_t)colbase * 2;
    u32 wsm = (u32)__cvta_generic_to_shared(Ws);
    const int NSB = KSEG / 16;

    auto issue = [&](int sb) {
        if (sb < NSB) {
            const float* src = wsrc + (size_t)sb * 8 * N2;
            u32 dst = wsm + (u32)((sb % 3) * 2048 * 4);
            #pragma unroll
            for (int i = 0; i < 2; ++i) {
                int f = i * 256 + tid;
                int r = f >> 6;
                int c = (f & 63) << 2;
                cp_async16(dst + (u32)(r * 256 + c) * 4, src + (size_t)r * N2 + c);
            }
        }
        cp_commit();
    };
    issue(0); issue(1);
    __syncthreads();

    int j0 = colbase + cg, j1 = j0 + 64;
    bool v0 = (j0 < N), v1 = (j1 < N);
    int b0 = bg * 8;

    ull acc0[8], acc1[8];
    #pragma unroll
    for (int i = 0; i < 8; ++i) { acc0[i] = 0ull; acc1[i] = 0ull; }

    for (int sb = 0; sb < NSB; ++sb) {
        cp_wait<1>();
        __syncthreads();
        const float* W0 = Ws + (sb % 3) * 2048;
        int kk = sb * 16;
        #pragma unroll
        for (int kp2 = 0; kp2 < 4; ++kp2) {
            ull wa0 = *reinterpret_cast<const ull*>(W0 + (kp2*2    ) * 256 + cg * 2);
            ull wa1 = *reinterpret_cast<const ull*>(W0 + (kp2*2 + 1) * 256 + cg * 2);
            ull wb0 = *reinterpret_cast<const ull*>(W0 + (kp2*2    ) * 256 + 128 + cg * 2);
            ull wb1 = *reinterpret_cast<const ull*>(W0 + (kp2*2 + 1) * 256 + 128 + cg * 2);
            #pragma unroll
            for (int i = 0; i < 8; ++i) {
                ulonglong2 xv = *reinterpret_cast<const ulonglong2*>(&Xs[(b0 + i) * KSEG + kk + kp2 * 4]);
                acc0[i] = ffma2(xv.x, wa0, acc0[i]);
                acc0[i] = ffma2(xv.y, wa1, acc0[i]);
                acc1[i] = ffma2(xv.x, wb0, acc1[i]);
                acc1[i] = ffma2(xv.y, wb1, acc1[i]);
            }
        }
        __syncthreads();
        issue(sb + 2);
    }

    float* pp = part + ((size_t)seg * 32 + b0) * npad;
    #pragma unroll
    for (int i = 0; i < 8; ++i) {
        if (v0) pp[(size_t)i * npad + j0] = pairsum(acc0[i]);
        if (v1) pp[(size_t)i * npad + j1] = pairsum(acc1[i]);
    }
}

// -------- setup --------
__global__ void k_setup(const int* __restrict__ lens, const int* __restrict__ caps_in,
                        float* __restrict__ out) {
    __shared__ int s_len[BB];
    __shared__ int s_si[BB];
    int tid = threadIdx.x;
    if (tid < BB) s_len[tid] = lens[tid];
    __syncthreads();
    if (tid < BB) {
        int li = s_len[tid];
        int r = 0;
        for (int j = 0; j < BB; ++j) {
            int lj = s_len[j];
            if (lj > li || (lj == li && j < tid)) r++;
        }
        s_si[r] = tid;
    }
    __syncthreads();
    if (tid < BB) {
        int si = s_si[tid];
        g_sortind[tid] = si;
        g_declen[tid]  = s_len[si] - 1;
        out[OFF_SORT + tid] = (float)si;
    }
    __syncthreads();
    for (int i = tid; i < BB*LLL; i += blockDim.x) {
        int b = i / LLL, w = i % LLL;
        int cv = caps_in[s_si[b]*LLL + w];
        g_caps[i] = cv;
        out[OFF_CAPS + i] = (float)cv;
    }
}

// -------- one-time weight packing --------
__global__ void k_pack(const float* __restrict__ W_ih, const float* __restrict__ W_hh,
                       const float* __restrict__ W_fc, const float* __restrict__ W_fbeta,
                       const float* __restrict__ W_dec,
                       const float* __restrict__ Wih0, const float* __restrict__ Wic0) {
    const long long TA = (long long)KCC * G4;
    const long long TB = (long long)DD * NBIG;
    long long idx = (long long)blockIdx.x * 256 + threadIdx.x;
    if (idx < TA) {
        long long a = idx;
        int kp = (int)(a / (2*G4));
        int rem = (int)(a % (2*G4));
        int j = rem >> 1;
        int k = kp*2 + (rem & 1);
        float v = (k < 2560) ? W_ih[(size_t)j*2560 + k] : W_hh[(size_t)j*512 + (k - 2560)];
        g_wcomb[a] = v;
    } else if (idx < TA + TB) {
        long long b = idx - TA;
        int kp = (int)(b / (2*NBIG));
        int rem = (int)(b % (2*NBIG));
        int j = rem >> 1;
        int k = kp*2 + (rem & 1);
        float v;
        if (j < 2048)         v = W_fbeta[(size_t)k*EE + j];
        else if (j < COL_FC)  v = W_dec[(size_t)k*AA + (j - 2048)];
        else                  v = W_fc[(size_t)k*VV + (j - COL_FC)];
        g_wbig[b] = v;
    } else {
        long long c = idx - TA - TB;
        int kp = (int)(c >> 11);
        int rem = (int)(c & 2047);
        int j = rem >> 1;
        int k = kp*2 + (rem & 1);
        float v = (j < 512) ? Wih0[(size_t)k*512 + j] : Wic0[(size_t)k*512 + (j - 512)];
        g_wic[c] = v;
    }
}

// -------- mean over pixels --------
__global__ void k_mean(const float* __restrict__ enc) {
    int b = blockIdx.y;
    int j = (blockIdx.x * 128 + threadIdx.x) * 4;
    int sb = g_sortind[b];
    const float* base = enc + (size_t)sb * PP * EE + j;
    float4 s = make_float4(0.f, 0.f, 0.f, 0.f);
    #pragma unroll 4
    for (int p = 0; p < PP; ++p) {
        float4 v = *reinterpret_cast<const float4*>(base + (size_t)p * EE);
        s.x += v.x; s.y += v.y; s.z += v.z; s.w += v.w;
    }
    const float inv = 1.0f / 196.0f;
    s.x *= inv; s.y *= inv; s.z *= inv; s.w *= inv;
    *reinterpret_cast<float4*>(&g_mean[b*EE + j]) = s;
}

// -------- init GEMM: mean @ wic --------
__global__ __launch_bounds__(256, 3)
void k_gemm_init() {
    __shared__ __align__(16) float Xs[32*128];
    __shared__ __align__(16) float Ws[3*2048];
    __shared__ const float* rowp[32];
    int kb = blockIdx.y * 128;
    if (threadIdx.x < 32) rowp[threadIdx.x] = g_mean + threadIdx.x * EE + kb;
    gemm4r<128>(Xs, Ws, rowp, g_wic, 2048, g_part, 1024, 1024,
                blockIdx.x, blockIdx.y, 0);
}

// -------- merged: attn (blocks 0..31, att2 computed in-block) + gate GEMM ----
__global__ __launch_bounds__(256, 2)
void k_attn2(const float* __restrict__ W_dec, const float* __restrict__ b_dec,
             const float* __restrict__ W_full, const float* __restrict__ b_full,
             float* __restrict__ out, int t) {
    __shared__ __align__(16) float smem[4096 + 6144];
    __shared__ const float* rowp[32];
    int tid = threadIdx.x;
    int bid = blockIdx.x;

    if (bid >= 32) {
        // gate GEMM: h @ wbig[:,0:2048), K=512 -> 4 segs of 128, 16 chunks
        int q = bid - 32;
        int chunk = q & 15, seg = q >> 4;
        if (tid < 32) rowp[tid] = g_h + tid * DD + seg * 128;
        gemm4r<128>(smem, smem + 4096, rowp, g_wbig, 2*NBIG, g_part2, NBIG, NBIG,
                    chunk, seg, COL_GATE);
        return;
    }

    int b = bid;
    float* hs    = smem;          // 512
    float* att2s = smem + 512;    // 512
    float* wfs   = smem + 1024;   // 512
    float* es    = smem + 1536;   // 256 (196 used)
    float* red   = smem + 1792;   // 256

    hs[tid] = g_h[b*DD + tid]; hs[tid + 256] = g_h[b*DD + tid + 256];
    wfs[tid] = W_full[tid];    wfs[tid + 256] = W_full[tid + 256];
    __syncthreads();

    // att2 pair for cols (2c, 2c+1): f32x2 over col pairs, k ascending
    {
        int c2 = tid * 2;
        ull acc = 0ull;
        const float* wdp = W_dec + c2;
        #pragma unroll 8
        for (int k = 0; k < DD; ++k) {
            ull w = *reinterpret_cast<const ull*>(wdp + (size_t)k * AA);
            acc = ffma2(dup2(hs[k]), w, acc);
        }
        float2 r = *reinterpret_cast<float2*>(&acc);
        att2s[c2]     = r.x + b_dec[c2];
        att2s[c2 + 1] = r.y + b_dec[c2 + 1];
    }
    __syncthreads();

    int w = tid >> 5, lane = tid & 31;
    float bf = b_full[0];
    for (int p = w; p < PP; p += 8) {
        const float4* row4 = reinterpret_cast<const float4*>(g_att1 + ((size_t)b * PP + p) * AA);
        const float4* a24  = reinterpret_cast<const float4*>(att2s);
        const float4* wf4  = reinterpret_cast<const float4*>(wfs);
        float part = 0.0f;
        #pragma unroll
        for (int i = 0; i < 4; ++i) {
            int a = lane + i * 32;
            float4 v = row4[a];
            float4 t2 = a24[a];
            float4 wf = wf4[a];
            part = fmaf(fmaxf(v.x + t2.x, 0.f), wf.x, part);
            part = fmaf(fmaxf(v.y + t2.y, 0.f), wf.y, part);
            part = fmaf(fmaxf(v.z + t2.z, 0.f), wf.z, part);
            part = fmaf(fmaxf(v.w + t2.w, 0.f), wf.w, part);
        }
        #pragma unroll
        for (int off = 16; off; off >>= 1) part += __shfl_down_sync(0xffffffffu, part, off);
        if (lane == 0) es[p] = part + bf;
    }
    __syncthreads();

    float v = (tid < PP) ? es[tid] : -1e30f;
    red[tid] = v; __syncthreads();
    for (int s = 128; s > 0; s >>= 1) { if (tid < s) red[tid] = fmaxf(red[tid], red[tid+s]); __syncthreads(); }
    float mx = red[0]; __syncthreads();
    float ex = (tid < PP) ? expf(v - mx) : 0.0f;
    red[tid] = ex; __syncthreads();
    for (int s = 128; s > 0; s >>= 1) { if (tid < s) red[tid] += red[tid+s]; __syncthreads(); }
    float inv = 1.0f / red[0];
    if (tid < PP) {
        float alpha = ex * inv;
        g_alpha[b*PP + tid] = alpha;
        float m = (g_declen[b] > t) ? 1.0f : 0.0f;
        out[OFF_ALPHA + ((size_t)b*TTT + t)*PP + tid] = alpha * m;
    }
}

// -------- staging: g_x2 = gate*awe (2048 cols); gate from part2 segs 0..3 ----
__global__ void k_stage(const float* __restrict__ enc, const float* __restrict__ b_fbeta,
                        int t) {
    __shared__ float al[PP];
    int b = blockIdx.y;
    int tid = threadIdx.x;
    for (int i = tid; i < PP; i += 128) al[i] = g_alpha[b*PP + i];
    __syncthreads();

    int j = blockIdx.x * 128 + tid;   // < 2048
    int sb = g_sortind[b];
    const float* eb = enc + (size_t)sb * PP * EE + j;
    float awe0 = 0.f, awe1 = 0.f;
    #pragma unroll 8
    for (int p = 0; p < 192; p += 2) {
        awe0 = fmaf(al[p],     eb[(size_t)p * EE],       awe0);
        awe1 = fmaf(al[p + 1], eb[(size_t)(p + 1) * EE], awe1);
    }
    awe0 = fmaf(al[192], eb[(size_t)192 * EE], awe0);
    awe1 = fmaf(al[193], eb[(size_t)193 * EE], awe1);
    awe0 = fmaf(al[194], eb[(size_t)194 * EE], awe0);
    awe1 = fmaf(al[195], eb[(size_t)195 * EE], awe1);
    float awe = awe0 + awe1;
    float ga = b_fbeta[j];
    #pragma unroll
    for (int s = 0; s < 4; ++s)
        ga += g_part2[((size_t)s * 32 + b) * NBIG + COL_GATE + j];
    g_x2[b*2048 + j] = awe * sigm(ga);
}

// -------- gates(t) [384 blocks] + preds(t-1) [316 blocks] --------------------
__global__ __launch_bounds__(256, 3)
void k_gemm_gates_preds(const float* __restrict__ emb, int t) {
    __shared__ __align__(16) float Xs[32*128];
    __shared__ __align__(16) float Ws[3*2048];
    __shared__ const float* rowp[32];
    int bid = blockIdx.x;
    int tid = threadIdx.x;
    if (bid < 384) {
        int chunk = bid & 15, seg = bid >> 4;
        if (tid < 32) {
            int kb = seg * 128;
            const float* p;
            if (seg < 4)       p = emb + (size_t)g_caps[tid*LLL + t] * MMM + kb;
            else if (seg < 20) p = g_x2 + tid * 2048 + (kb - 512);
            else               p = g_h + tid * DD + (kb - 2560);
            rowp[tid] = p;
        }
        gemm4r<128>(Xs, Ws, rowp, g_wcomb, 2*G4, g_part, G4, G4, chunk, seg, 0);
    } else {
        int q = bid - 384;
        int chunk = q % 79, seg = q / 79;
        if (tid < 32) rowp[tid] = g_h + tid * DD + seg * 128;
        gemm4r<128>(Xs, Ws, rowp, g_wbig, 2*NBIG, g_part2, NBIG, NBIG,
                    chunk, seg, COL_FC);
    }
}

__global__ __launch_bounds__(256, 3)
void k_gemm_preds() {  // tail: preds(18)
    __shared__ __align__(16) float Xs[32*128];
    __shared__ __align__(16) float Ws[3*2048];
    __shared__ const float* rowp[32];
    int q = blockIdx.x;
    int chunk = q % 79, seg = q / 79;
    if (threadIdx.x < 32) rowp[threadIdx.x] = g_h + threadIdx.x * DD + seg * 128;
    gemm4r<128>(Xs, Ws, rowp, g_wbig, 2*NBIG, g_part2, NBIG, NBIG,
                chunk, seg, COL_FC);
}

// -------- init epilogue --------
__global__ void k_init_fin(const float* __restrict__ b_init_h, const float* __restrict__ b_init_c) {
    int idx = blockIdx.x * blockDim.x + threadIdx.x;
    int b = idx >> 9, d = idx & 511;
    float h = b_init_h[d], c = b_init_c[d];
    #pragma unroll
    for (int s = 0; s < 16; ++s) {
        h += g_part[(s*32 + b)*1024 + d];
        c += g_part[(s*32 + b)*1024 + 512 + d];
    }
    g_h[idx] = h;
    g_c[idx] = c;
}

// -------- att1: [6272,2048]x[2048,512] f32x2 SGEMM, 128x64 tiles -------------
__global__ __launch_bounds__(128, 3)
void k_att1(const float* __restrict__ enc, const float* __restrict__ W,
            const float* __restrict__ bias) {
    __shared__ __align__(16) float As[16][128];
    __shared__ __align__(16) float Bs[16][64];
    int tid = threadIdx.x;
    int rowBase = blockIdx.x * 128;
    int colBase = blockIdx.y * 64;

    int grow = rowBase + tid;
    const float* asrc = enc + ((size_t)g_sortind[grow / PP] * PP + (grow % PP)) * EE;
    int bk0 = (tid >> 4) * 2;
    int bn  = (tid & 15) * 4;
    const float* bsrc = W + (size_t)bk0 * AA + colBase + bn;

    int m0 = (tid >> 3) * 8;
    int n0 = (tid & 7) * 8;

    ull acc[8][4];
    #pragma unroll
    for (int i = 0; i < 8; ++i)
        #pragma unroll
        for (int j = 0; j < 4; ++j) acc[i][j] = 0ull;

    float4 pa[4];
    #pragma unroll
    for (int u = 0; u < 4; ++u) pa[u] = *reinterpret_cast<const float4*>(asrc + 4*u);
    float4 pb0 = *reinterpret_cast<const float4*>(bsrc);
    float4 pb1 = *reinterpret_cast<const float4*>(bsrc + AA);

    for (int kb = 0; kb < EE; kb += 16) {
        #pragma unroll
        for (int u = 0; u < 4; ++u) {
            As[4*u + 0][tid] = pa[u].x;
            As[4*u + 1][tid] = pa[u].y;
            As[4*u + 2][tid] = pa[u].z;
            As[4*u + 3][tid] = pa[u].w;
        }
        *reinterpret_cast<float4*>(&Bs[bk0][bn])     = pb0;
        *reinterpret_cast<float4*>(&Bs[bk0 + 1][bn]) = pb1;
        __syncthreads();
        if (kb + 16 < EE) {
            #pragma unroll
            for (int u = 0; u < 4; ++u)
                pa[u] = *reinterpret_cast<const float4*>(asrc + kb + 16 + 4*u);
            pb0 = *reinterpret_cast<const float4*>(bsrc + (size_t)(kb + 16) * AA);
            pb1 = *reinterpret_cast<const float4*>(bsrc + (size_t)(kb + 17) * AA);
        }
        #pragma unroll
        for (int k = 0; k < 16; ++k) {
            float4 a0 = *reinterpret_cast<const float4*>(&As[k][m0]);
            float4 a1 = *reinterpret_cast<const float4*>(&As[k][m0 + 4]);
            ulonglong2 bp0 = *reinterpret_cast<const ulonglong2*>(&Bs[k][n0]);
            ulonglong2 bp1 = *reinterpret_cast<const ulonglong2*>(&Bs[k][n0 + 4]);
            float am[8] = {a0.x, a0.y, a0.z, a0.w, a1.x, a1.y, a1.z, a1.w};
            #pragma unroll
            for (int i = 0; i < 8; ++i) {
                ull ad = dup2(am[i]);
                acc[i][0] = ffma2(ad, bp0.x, acc[i][0]);
                acc[i][1] = ffma2(ad, bp0.y, acc[i][1]);
                acc[i][2] = ffma2(ad, bp1.x, acc[i][2]);
                acc[i][3] = ffma2(ad, bp1.y, acc[i][3]);
            }
        }
        __syncthreads();
    }
    float2 bb[4];
    #pragma unroll
    for (int jp = 0; jp < 4; ++jp)
        bb[jp] = *reinterpret_cast<const float2*>(bias + colBase + n0 + 2*jp);
    #pragma unroll
    for (int i = 0; i < 8; ++i) {
        int row = rowBase + m0 + i;
        #pragma unroll
        for (int jp = 0; jp < 4; ++jp) {
            float2 r = *reinterpret_cast<float2*>(&acc[i][jp]);
            float2 o = make_float2(r.x + bb[jp].x, r.y + bb[jp].y);
            *reinterpret_cast<float2*>(&g_att1[(size_t)row * AA + colBase + n0 + 2*jp]) = o;
        }
    }
}

// -------- fin helper --------
__device__ __forceinline__ void fin_body(const float* __restrict__ b_fc,
                                         float* __restrict__ out, int t,
                                         int b, int j) {
    if (j >= VV) return;
    float v = 0.0f;
    if (g_declen[b] > t) {
        v = b_fc[j];
        #pragma unroll
        for (int s = 0; s < 4; ++s)
            v += g_part2[((size_t)s * 32 + b) * NBIG + COL_FC + j];
    }
    out[OFF_PRED + ((size_t)b*TTT + t)*VV + j] = v;
}

// -------- merged lstm(t) + fin(t-1) --------
__global__ void k_lstm_fin(const float* __restrict__ b_ih, const float* __restrict__ b_hh,
                           const float* __restrict__ b_fc, float* __restrict__ out, int t) {
    int bid = blockIdx.x;
    int tid = threadIdx.x;
    if (bid < 64) {
        int idx = bid * 256 + tid;
        int b = idx >> 9, d = idx & 511;
        float s[4];
        #pragma unroll
        for (int g = 0; g < 4; ++g) {
            float acc = b_ih[g*512 + d] + b_hh[g*512 + d];
            #pragma unroll
            for (int seg = 0; seg < 24; ++seg)
                acc += g_part[((size_t)seg * 32 + b) * G4 + g*512 + d];
            s[g] = acc;
        }
        float ig = sigm(s[0]), fg = sigm(s[1]), gg = tanhf(s[2]), og = sigm(s[3]);
        float cn = fg * g_c[idx] + ig * gg;
        float hn = og * tanhf(cn);
        if (g_declen[b] > t) { g_h[idx] = hn; g_c[idx] = cn; }
    } else {
        int tprev = t - 1;
        if (tprev < 0) return;
        int q = bid - 64;
        int b = q / 40;
        int j = (q % 40) * 256 + tid;
        fin_body(b_fc, out, tprev, b, j);
    }
}

__global__ void k_fin_tail(const float* __restrict__ b_fc, float* __restrict__ out) {
    int b = blockIdx.y;
    int j = blockIdx.x * 256 + threadIdx.x;
    fin_body(b_fc, out, TTT - 1, b, j);
}

// ============================================================================
extern "C" void kernel_launch(void* const* d_in, const int* in_sizes, int n_in,
                              void* d_out, int out_size) {
    const float* enc       = (const float*)d_in[0];
    const int*   caps_in   = (const int*)  d_in[1];
    const int*   lens      = (const int*)  d_in[2];
    const float* W_enc_att = (const float*)d_in[3];
    const float* b_enc_att = (const float*)d_in[4];
    const float* W_dec_att = (const float*)d_in[5];
    const float* b_dec_att = (const float*)d_in[6];
    const float* W_full    = (const float*)d_in[7];
    const float* b_full    = (const float*)d_in[8];
    const float* emb       = (const float*)d_in[9];
    const float* W_ih      = (const float*)d_in[10];
    const float* W_hh      = (const float*)d_in[11];
    const float* b_ih      = (const float*)d_in[12];
    const float* b_hh      = (const float*)d_in[13];
    const float* W_init_h  = (const float*)d_in[14];
    const float* b_init_h  = (const float*)d_in[15];
    const float* W_init_c  = (const float*)d_in[16];
    const float* b_init_c  = (const float*)d_in[17];
    const float* W_fbeta   = (const float*)d_in[18];
    const float* b_fbeta   = (const float*)d_in[19];
    const float* W_fc      = (const float*)d_in[20];
    const float* b_fc      = (const float*)d_in[21];
    float* out = (float*)d_out;

    k_setup<<<1, 32>>>(lens, caps_in, out);
    k_pack<<<57888, 256>>>(W_ih, W_hh, W_fc, W_fbeta, W_dec_att, W_init_h, W_init_c);
    k_mean<<<dim3(4, BB), 128>>>(enc);
    k_gemm_init<<<dim3(8, 16), 256>>>();
    k_init_fin<<<64, 256>>>(b_init_h, b_init_c);
    k_att1<<<dim3(49, 8), 128>>>(enc, W_enc_att, b_enc_att);

    for (int t = 0; t < TTT; ++t) {
        k_attn2<<<96, 256>>>(W_dec_att, b_dec_att, W_full, b_full, out, t);
        k_stage<<<dim3(16, BB), 128>>>(enc, b_fbeta, t);
        k_gemm_gates_preds<<<700, 256>>>(emb, t);
        k_lstm_fin<<<1344, 256>>>(b_ih, b_hh, b_fc, out, t);
    }
    k_gemm_preds<<<316, 256>>>();
    k_fin_tail<<<dim3(40, BB), 256>>>(b_fc, out);
    (void)in_sizes; (void)n_in; (void)out_size;
}

// round 9
// speedup vs baseline: 1.1566x; 1.1566x over previous
#include <cuda_runtime.h>
#include <stdint.h>
#include <math.h>

#define BB 32
#define PP 196
#define EE 2048
#define AA 512
#define DD 512
#define MMM 512
#define VV 10000
#define LLL 20
#define TTT 19
#define KCC 3072
#define G4 2048
#define NBIG 12560 /* fbeta | dec_att | fc */

#define OFF_PRED  0
#define OFF_CAPS  (BB*TTT*VV)
#define OFF_ALPHA (OFF_CAPS + BB*LLL)
#define OFF_SORT  (OFF_ALPHA + BB*TTT*PP)

#define COL_GATE 0
#define COL_ATT2 2048
#define COL_FC   2560

typedef unsigned long long ull;
typedef unsigned int u32;

// -------- scratch --------
__device__ float g_att1[BB*PP*AA];
__device__ float g_wcomb[KCC*G4 + 2048];   // [W_ih | W_hh] k-pair-interleaved
__device__ float g_wic[EE*1024 + 2048];    // [W_init_h | W_init_c]
__device__ float g_wbig[DD*NBIG + 4096];   // [W_fbeta | W_dec_att | W_fc]
__device__ float g_mean[BB*EE];
__device__ float g_h[BB*DD];
__device__ float g_c[BB*DD];
__device__ float g_alpha[BB*PP];
__device__ float g_x2[BB*2048];            // gate*awe
__device__ float g_part[24*BB*G4];
__device__ float g_part2[4*BB*NBIG];
__device__ int   g_sortind[BB];
__device__ int   g_declen[BB];
__device__ int   g_caps[BB*LLL];

__device__ __forceinline__ float sigm(float x) { return 1.0f / (1.0f + expf(-x)); }

__device__ __forceinline__ ull ffma2(ull a, ull b, ull c) {
    ull d;
    asm("fma.rn.f32x2 %0, %1, %2, %3;" : "=l"(d) : "l"(a), "l"(b), "l"(c));
    return d;
}
__device__ __forceinline__ float pairsum(ull v) {
    float2 f = *reinterpret_cast<float2*>(&v);
    return f.x + f.y;
}
__device__ __forceinline__ ull dup2(float a) {
    ull r;
    asm("mov.b64 %0, {%1, %1};" : "=l"(r) : "f"(a));
    return r;
}
__device__ __forceinline__ void cp_async16(u32 smem_addr, const void* gptr) {
    asm volatile("cp.async.cg.shared.global [%0], [%1], 16;" :: "r"(smem_addr), "l"(gptr));
}
__device__ __forceinline__ void cp_commit() {
    asm volatile("cp.async.commit_group;" ::: "memory");
}
template<int N> __device__ __forceinline__ void cp_wait() {
    asm volatile("cp.async.wait_group %0;" :: "n"(N) : "memory");
}

// ============ cp.async skinny-GEMM body (KSEG=128), row-pointer X loader =====
__device__ __forceinline__ void gemm4r(
    float* Xs, float* Ws, const float* const* rowp,
    const float* __restrict__ Wp, int N2,
    float* __restrict__ part, int npad, int N,
    int chunk, int seg, int colOffset)
{
    const int KSEG = 128;
    int tid = threadIdx.x;
    int cg = tid & 63, bg = tid >> 6;
    int colbase = colOffset + chunk * 128;
    int kb = seg * KSEG;

    __syncthreads();   // rowp ready

    #pragma unroll
    for (int i = 0; i < 4; ++i) {
        int f = i * 256 + tid;
        int r = f >> 5;
        int c4 = (f & 31) * 4;
        *reinterpret_cast<float4*>(&Xs[r * KSEG + c4]) =
            *reinterpret_cast<const float4*>(rowp[r] + c4);
    }

    const float* wsrc = Wp + (size_t)(kb >> 1) * N2 + (size_t)colbase * 2;
    u32 wsm = (u32)__cvta_generic_to_shared(Ws);
    const int NSB = 8;

    auto issue = [&](int sb) {
        if (sb < NSB) {
            const float* src = wsrc + (size_t)sb * 8 * N2;
            u32 dst = wsm + (u32)((sb % 3) * 2048 * 4);
            #pragma unroll
            for (int i = 0; i < 2; ++i) {
                int f = i * 256 + tid;
                int r = f >> 6;
                int c = (f & 63) << 2;
                cp_async16(dst + (u32)(r * 256 + c) * 4, src + (size_t)r * N2 + c);
            }
        }
        cp_commit();
    };
    issue(0); issue(1);
    __syncthreads();

    int j0 = colbase + cg, j1 = j0 + 64;
    bool v0 = (j0 < N), v1 = (j1 < N);
    int b0 = bg * 8;

    ull acc0[8], acc1[8];
    #pragma unroll
    for (int i = 0; i < 8; ++i) { acc0[i] = 0ull; acc1[i] = 0ull; }

    for (int sb = 0; sb < NSB; ++sb) {
        cp_wait<1>();
        __syncthreads();
        const float* W0 = Ws + (sb % 3) * 2048;
        int kk = sb * 16;
        #pragma unroll
        for (int kp2 = 0; kp2 < 4; ++kp2) {
            ull wa0 = *reinterpret_cast<const ull*>(W0 + (kp2*2    ) * 256 + cg * 2);
            ull wa1 = *reinterpret_cast<const ull*>(W0 + (kp2*2 + 1) * 256 + cg * 2);
            ull wb0 = *reinterpret_cast<const ull*>(W0 + (kp2*2    ) * 256 + 128 + cg * 2);
            ull wb1 = *reinterpret_cast<const ull*>(W0 + (kp2*2 + 1) * 256 + 128 + cg * 2);
            #pragma unroll
            for (int i = 0; i < 8; ++i) {
                ulonglong2 xv = *reinterpret_cast<const ulonglong2*>(&Xs[(b0 + i) * KSEG + kk + kp2 * 4]);
                acc0[i] = ffma2(xv.x, wa0, acc0[i]);
                acc0[i] = ffma2(xv.y, wa1, acc0[i]);
                acc1[i] = ffma2(xv.x, wb0, acc1[i]);
                acc1[i] = ffma2(xv.y, wb1, acc1[i]);
            }
        }
        __syncthreads();
        issue(sb + 2);
    }

    float* pp = part + ((size_t)seg * 32 + b0) * npad;
    #pragma unroll
    for (int i = 0; i < 8; ++i) {
        if (v0) pp[(size_t)i * npad + j0] = pairsum(acc0[i]);
        if (v1) pp[(size_t)i * npad + j1] = pairsum(acc1[i]);
    }
}

// -------- setup --------
__global__ void k_setup(const int* __restrict__ lens, const int* __restrict__ caps_in,
                        float* __restrict__ out) {
    __shared__ int s_len[BB];
    __shared__ int s_si[BB];
    int tid = threadIdx.x;
    if (tid < BB) s_len[tid] = lens[tid];
    __syncthreads();
    if (tid < BB) {
        int li = s_len[tid];
        int r = 0;
        for (int j = 0; j < BB; ++j) {
            int lj = s_len[j];
            if (lj > li || (lj == li && j < tid)) r++;
        }
        s_si[r] = tid;
    }
    __syncthreads();
    if (tid < BB) {
        int si = s_si[tid];
        g_sortind[tid] = si;
        g_declen[tid]  = s_len[si] - 1;
        out[OFF_SORT + tid] = (float)si;
    }
    __syncthreads();
    for (int i = tid; i < BB*LLL; i += blockDim.x) {
        int b = i / LLL, w = i % LLL;
        int cv = caps_in[s_si[b]*LLL + w];
        g_caps[i] = cv;
        out[OFF_CAPS + i] = (float)cv;
    }
}

// -------- one-time weight packing --------
__global__ void k_pack(const float* __restrict__ W_ih, const float* __restrict__ W_hh,
                       const float* __restrict__ W_fc, const float* __restrict__ W_fbeta,
                       const float* __restrict__ W_dec,
                       const float* __restrict__ Wih0, const float* __restrict__ Wic0) {
    const long long TA = (long long)KCC * G4;
    const long long TB = (long long)DD * NBIG;
    long long idx = (long long)blockIdx.x * 256 + threadIdx.x;
    if (idx < TA) {
        long long a = idx;
        int kp = (int)(a / (2*G4));
        int rem = (int)(a % (2*G4));
        int j = rem >> 1;
        int k = kp*2 + (rem & 1);
        float v = (k < 2560) ? W_ih[(size_t)j*2560 + k] : W_hh[(size_t)j*512 + (k - 2560)];
        g_wcomb[a] = v;
    } else if (idx < TA + TB) {
        long long b = idx - TA;
        int kp = (int)(b / (2*NBIG));
        int rem = (int)(b % (2*NBIG));
        int j = rem >> 1;
        int k = kp*2 + (rem & 1);
        float v;
        if (j < COL_ATT2)     v = W_fbeta[(size_t)k*EE + j];
        else if (j < COL_FC)  v = W_dec[(size_t)k*AA + (j - COL_ATT2)];
        else                  v = W_fc[(size_t)k*VV + (j - COL_FC)];
        g_wbig[b] = v;
    } else {
        long long c = idx - TA - TB;
        int kp = (int)(c >> 11);
        int rem = (int)(c & 2047);
        int j = rem >> 1;
        int k = kp*2 + (rem & 1);
        float v = (j < 512) ? Wih0[(size_t)k*512 + j] : Wic0[(size_t)k*512 + (j - 512)];
        g_wic[c] = v;
    }
}

// -------- mean over pixels --------
__global__ void k_mean(const float* __restrict__ enc) {
    int b = blockIdx.y;
    int j = (blockIdx.x * 128 + threadIdx.x) * 4;
    int sb = g_sortind[b];
    const float* base = enc + (size_t)sb * PP * EE + j;
    float4 s = make_float4(0.f, 0.f, 0.f, 0.f);
    #pragma unroll 4
    for (int p = 0; p < PP; ++p) {
        float4 v = *reinterpret_cast<const float4*>(base + (size_t)p * EE);
        s.x += v.x; s.y += v.y; s.z += v.z; s.w += v.w;
    }
    const float inv = 1.0f / 196.0f;
    s.x *= inv; s.y *= inv; s.z *= inv; s.w *= inv;
    *reinterpret_cast<float4*>(&g_mean[b*EE + j]) = s;
}

// -------- init GEMM: mean @ wic --------
__global__ __launch_bounds__(256, 3)
void k_gemm_init() {
    __shared__ __align__(16) float Xs[32*128];
    __shared__ __align__(16) float Ws[3*2048];
    __shared__ const float* rowp[32];
    int kb = blockIdx.y * 128;
    if (threadIdx.x < 32) rowp[threadIdx.x] = g_mean + threadIdx.x * EE + kb;
    gemm4r(Xs, Ws, rowp, g_wic, 2048, g_part, 1024, 1024,
           blockIdx.x, blockIdx.y, 0);
}

// -------- init epilogue --------
__global__ void k_init_fin(const float* __restrict__ b_init_h, const float* __restrict__ b_init_c) {
    int idx = blockIdx.x * blockDim.x + threadIdx.x;
    int b = idx >> 9, d = idx & 511;
    float h = b_init_h[d], c = b_init_c[d];
    #pragma unroll
    for (int s = 0; s < 16; ++s) {
        h += g_part[(s*32 + b)*1024 + d];
        c += g_part[(s*32 + b)*1024 + 512 + d];
    }
    g_h[idx] = h;
    g_c[idx] = c;
}

// -------- att1: [6272,2048]x[2048,512] f32x2 SGEMM, 128x64 tiles -------------
__global__ __launch_bounds__(128, 3)
void k_att1(const float* __restrict__ enc, const float* __restrict__ W,
            const float* __restrict__ bias) {
    __shared__ __align__(16) float As[16][128];
    __shared__ __align__(16) float Bs[16][64];
    int tid = threadIdx.x;
    int rowBase = blockIdx.x * 128;
    int colBase = blockIdx.y * 64;

    int grow = rowBase + tid;
    const float* asrc = enc + ((size_t)g_sortind[grow / PP] * PP + (grow % PP)) * EE;
    int bk0 = (tid >> 4) * 2;
    int bn  = (tid & 15) * 4;
    const float* bsrc = W + (size_t)bk0 * AA + colBase + bn;

    int m0 = (tid >> 3) * 8;
    int n0 = (tid & 7) * 8;

    ull acc[8][4];
    #pragma unroll
    for (int i = 0; i < 8; ++i)
        #pragma unroll
        for (int j = 0; j < 4; ++j) acc[i][j] = 0ull;

    float4 pa[4];
    #pragma unroll
    for (int u = 0; u < 4; ++u) pa[u] = *reinterpret_cast<const float4*>(asrc + 4*u);
    float4 pb0 = *reinterpret_cast<const float4*>(bsrc);
    float4 pb1 = *reinterpret_cast<const float4*>(bsrc + AA);

    for (int kb = 0; kb < EE; kb += 16) {
        #pragma unroll
        for (int u = 0; u < 4; ++u) {
            As[4*u + 0][tid] = pa[u].x;
            As[4*u + 1][tid] = pa[u].y;
            As[4*u + 2][tid] = pa[u].z;
            As[4*u + 3][tid] = pa[u].w;
        }
        *reinterpret_cast<float4*>(&Bs[bk0][bn])     = pb0;
        *reinterpret_cast<float4*>(&Bs[bk0 + 1][bn]) = pb1;
        __syncthreads();
        if (kb + 16 < EE) {
            #pragma unroll
            for (int u = 0; u < 4; ++u)
                pa[u] = *reinterpret_cast<const float4*>(asrc + kb + 16 + 4*u);
            pb0 = *reinterpret_cast<const float4*>(bsrc + (size_t)(kb + 16) * AA);
            pb1 = *reinterpret_cast<const float4*>(bsrc + (size_t)(kb + 17) * AA);
        }
        #pragma unroll
        for (int k = 0; k < 16; ++k) {
            float4 a0 = *reinterpret_cast<const float4*>(&As[k][m0]);
            float4 a1 = *reinterpret_cast<const float4*>(&As[k][m0 + 4]);
            ulonglong2 bp0 = *reinterpret_cast<const ulonglong2*>(&Bs[k][n0]);
            ulonglong2 bp1 = *reinterpret_cast<const ulonglong2*>(&Bs[k][n0 + 4]);
            float am[8] = {a0.x, a0.y, a0.z, a0.w, a1.x, a1.y, a1.z, a1.w};
            #pragma unroll
            for (int i = 0; i < 8; ++i) {
                ull ad = dup2(am[i]);
                acc[i][0] = ffma2(ad, bp0.x, acc[i][0]);
                acc[i][1] = ffma2(ad, bp0.y, acc[i][1]);
                acc[i][2] = ffma2(ad, bp1.x, acc[i][2]);
                acc[i][3] = ffma2(ad, bp1.y, acc[i][3]);
            }
        }
        __syncthreads();
    }
    float2 bb[4];
    #pragma unroll
    for (int jp = 0; jp < 4; ++jp)
        bb[jp] = *reinterpret_cast<const float2*>(bias + colBase + n0 + 2*jp);
    #pragma unroll
    for (int i = 0; i < 8; ++i) {
        int row = rowBase + m0 + i;
        #pragma unroll
        for (int jp = 0; jp < 4; ++jp) {
            float2 r = *reinterpret_cast<float2*>(&acc[i][jp]);
            float2 o = make_float2(r.x + bb[jp].x, r.y + bb[jp].y);
            *reinterpret_cast<float2*>(&g_att1[(size_t)row * AA + colBase + n0 + 2*jp]) = o;
        }
    }
}

// -------- per-step attention (att2 from part2 cols [2048,2560), 4 segs) ------
__global__ void k_attn(const float* __restrict__ b_dec, const float* __restrict__ W_full,
                       const float* __restrict__ b_full, float* __restrict__ out, int t) {
    __shared__ __align__(16) float att2s[AA];
    __shared__ __align__(16) float wfs[AA];
    __shared__ float es[PP];
    __shared__ float red[256];
    int b = blockIdx.x;
    int tid = threadIdx.x;

    #pragma unroll
    for (int cc = 0; cc < 2; ++cc) {
        int c = tid + cc * 256;
        float a2 = b_dec[c];
        #pragma unroll
        for (int s = 0; s < 4; ++s)
            a2 += g_part2[((size_t)s * 32 + b) * NBIG + COL_ATT2 + c];
        att2s[c] = a2;
        wfs[c] = W_full[c];
    }
    __syncthreads();

    int w = tid >> 5, lane = tid & 31;
    float bf = b_full[0];
    for (int p = w; p < PP; p += 8) {
        const float4* row4 = reinterpret_cast<const float4*>(g_att1 + ((size_t)b * PP + p) * AA);
        const float4* a24  = reinterpret_cast<const float4*>(att2s);
        const float4* wf4  = reinterpret_cast<const float4*>(wfs);
        float part = 0.0f;
        #pragma unroll
        for (int i = 0; i < 4; ++i) {
            int a = lane + i * 32;
            float4 v = row4[a];
            float4 t2 = a24[a];
            float4 wf = wf4[a];
            part = fmaf(fmaxf(v.x + t2.x, 0.f), wf.x, part);
            part = fmaf(fmaxf(v.y + t2.y, 0.f), wf.y, part);
            part = fmaf(fmaxf(v.z + t2.z, 0.f), wf.z, part);
            part = fmaf(fmaxf(v.w + t2.w, 0.f), wf.w, part);
        }
        #pragma unroll
        for (int off = 16; off; off >>= 1) part += __shfl_down_sync(0xffffffffu, part, off);
        if (lane == 0) es[p] = part + bf;
    }
    __syncthreads();

    float v = (tid < PP) ? es[tid] : -1e30f;
    red[tid] = v; __syncthreads();
    for (int s = 128; s > 0; s >>= 1) { if (tid < s) red[tid] = fmaxf(red[tid], red[tid+s]); __syncthreads(); }
    float mx = red[0]; __syncthreads();
    float ex = (tid < PP) ? expf(v - mx) : 0.0f;
    red[tid] = ex; __syncthreads();
    for (int s = 128; s > 0; s >>= 1) { if (tid < s) red[tid] += red[tid+s]; __syncthreads(); }
    float inv = 1.0f / red[0];
    if (tid < PP) {
        float alpha = ex * inv;
        g_alpha[b*PP + tid] = alpha;
        float m = (g_declen[b] > t) ? 1.0f : 0.0f;
        out[OFF_ALPHA + ((size_t)b*TTT + t)*PP + tid] = alpha * m;
    }
}

// -------- staging: g_x2 = gate*awe; gate from part2 segs 0..3 ----------------
__global__ void k_stage(const float* __restrict__ enc, const float* __restrict__ b_fbeta,
                        int t) {
    __shared__ float al[PP];
    int b = blockIdx.y;
    int tid = threadIdx.x;
    for (int i = tid; i < PP; i += 128) al[i] = g_alpha[b*PP + i];
    __syncthreads();

    int j = blockIdx.x * 128 + tid;   // < 2048
    int sb = g_sortind[b];
    const float* eb = enc + (size_t)sb * PP * EE + j;
    float awe0 = 0.f, awe1 = 0.f;
    #pragma unroll 8
    for (int p = 0; p < 192; p += 2) {
        awe0 = fmaf(al[p],     eb[(size_t)p * EE],       awe0);
        awe1 = fmaf(al[p + 1], eb[(size_t)(p + 1) * EE], awe1);
    }
    awe0 = fmaf(al[192], eb[(size_t)192 * EE], awe0);
    awe1 = fmaf(al[193], eb[(size_t)193 * EE], awe1);
    awe0 = fmaf(al[194], eb[(size_t)194 * EE], awe0);
    awe1 = fmaf(al[195], eb[(size_t)195 * EE], awe1);
    float awe = awe0 + awe1;
    float ga = b_fbeta[j];
    #pragma unroll
    for (int s = 0; s < 4; ++s)
        ga += g_part2[((size_t)s * 32 + b) * NBIG + COL_GATE + j];
    g_x2[b*2048 + j] = awe * sigm(ga);
}

// -------- gates(t) [384 blocks] + preds(t-1) [316 blocks] --------------------
__global__ __launch_bounds__(256, 3)
void k_gemm_gates_preds(const float* __restrict__ emb, int t) {
    __shared__ __align__(16) float Xs[32*128];
    __shared__ __align__(16) float Ws[3*2048];
    __shared__ const float* rowp[32];
    int bid = blockIdx.x;
    int tid = threadIdx.x;
    if (bid < 384) {
        int chunk = bid & 15, seg = bid >> 4;
        if (tid < 32) {
            int kb = seg * 128;
            const float* p;
            if (seg < 4)       p = emb + (size_t)g_caps[tid*LLL + t] * MMM + kb;
            else if (seg < 20) p = g_x2 + tid * 2048 + (kb - 512);
            else               p = g_h + tid * DD + (kb - 2560);
            rowp[tid] = p;
        }
        gemm4r(Xs, Ws, rowp, g_wcomb, 2*G4, g_part, G4, G4, chunk, seg, 0);
    } else {
        int q = bid - 384;
        int chunk = q % 79, seg = q / 79;
        if (tid < 32) rowp[tid] = g_h + tid * DD + seg * 128;
        gemm4r(Xs, Ws, rowp, g_wbig, 2*NBIG, g_part2, NBIG, NBIG,
               chunk, seg, COL_FC);
    }
}

__global__ __launch_bounds__(256, 3)
void k_gemm_preds() {  // tail: preds(18)
    __shared__ __align__(16) float Xs[32*128];
    __shared__ __align__(16) float Ws[3*2048];
    __shared__ const float* rowp[32];
    int q = blockIdx.x;
    int chunk = q % 79, seg = q / 79;
    if (threadIdx.x < 32) rowp[threadIdx.x] = g_h + threadIdx.x * DD + seg * 128;
    gemm4r(Xs, Ws, rowp, g_wbig, 2*NBIG, g_part2, NBIG, NBIG,
           chunk, seg, COL_FC);
}

// -------- LSTM pointwise (standalone, 64 blocks) -----------------------------
__global__ void k_lstm(const float* __restrict__ b_ih, const float* __restrict__ b_hh, int t) {
    int idx = blockIdx.x * 256 + threadIdx.x;
    int b = idx >> 9, d = idx & 511;
    float s[4];
    #pragma unroll
    for (int g = 0; g < 4; ++g) {
        float acc = b_ih[g*512 + d] + b_hh[g*512 + d];
        #pragma unroll
        for (int seg = 0; seg < 24; ++seg)
            acc += g_part[((size_t)seg * 32 + b) * G4 + g*512 + d];
        s[g] = acc;
    }
    float ig = sigm(s[0]), fg = sigm(s[1]), gg = tanhf(s[2]), og = sigm(s[3]);
    float cn = fg * g_c[idx] + ig * gg;
    float hn = og * tanhf(cn);
    if (g_declen[b] > t) { g_h[idx] = hn; g_c[idx] = cn; }
}

// -------- fin helper --------
__device__ __forceinline__ void fin_body(const float* __restrict__ b_fc,
                                         float* __restrict__ out, int t,
                                         int b, int j) {
    if (j >= VV) return;
    float v = 0.0f;
    if (g_declen[b] > t) {
        v = b_fc[j];
        #pragma unroll
        for (int s = 0; s < 4; ++s)
            v += g_part2[((size_t)s * 32 + b) * NBIG + COL_FC + j];
    }
    out[OFF_PRED + ((size_t)b*TTT + t)*VV + j] = v;
}

// -------- merged: small GEMM from new h [blocks 0..79] + fin(t-1) ------------
__global__ __launch_bounds__(256, 3)
void k_small_fin(const float* __restrict__ b_fc, float* __restrict__ out, int t) {
    __shared__ __align__(16) float Xs[32*128];
    __shared__ __align__(16) float Ws[3*2048];
    __shared__ const float* rowp[32];
    int bid = blockIdx.x;
    int tid = threadIdx.x;
    if (bid < 80) {
        int chunk = bid % 20, seg = bid / 20;
        if (tid < 32) rowp[tid] = g_h + tid * DD + seg * 128;
        gemm4r(Xs, Ws, rowp, g_wbig, 2*NBIG, g_part2, NBIG, NBIG,
               chunk, seg, COL_GATE);
    } else {
        int tprev = t - 1;
        if (tprev < 0) return;
        int q = bid - 80;
        int b = q / 40;
        int j = (q % 40) * 256 + tid;
        fin_body(b_fc, out, tprev, b, j);
    }
}

__global__ void k_fin_tail(const float* __restrict__ b_fc, float* __restrict__ out) {
    int b = blockIdx.y;
    int j = blockIdx.x * 256 + threadIdx.x;
    fin_body(b_fc, out, TTT - 1, b, j);
}

// ============================================================================
extern "C" void kernel_launch(void* const* d_in, const int* in_sizes, int n_in,
                              void* d_out, int out_size) {
    const float* enc       = (const float*)d_in[0];
    const int*   caps_in   = (const int*)  d_in[1];
    const int*   lens      = (const int*)  d_in[2];
    const float* W_enc_att = (const float*)d_in[3];
    const float* b_enc_att = (const float*)d_in[4];
    const float* W_dec_att = (const float*)d_in[5];
    const float* b_dec_att = (const float*)d_in[6];
    const float* W_full    = (const float*)d_in[7];
    const float* b_full    = (const float*)d_in[8];
    const float* emb       = (const float*)d_in[9];
    const float* W_ih      = (const float*)d_in[10];
    const float* W_hh      = (const float*)d_in[11];
    const float* b_ih      = (const float*)d_in[12];
    const float* b_hh      = (const float*)d_in[13];
    const float* W_init_h  = (const float*)d_in[14];
    const float* b_init_h  = (const float*)d_in[15];
    const float* W_init_c  = (const float*)d_in[16];
    const float* b_init_c  = (const float*)d_in[17];
    const float* W_fbeta   = (const float*)d_in[18];
    const float* b_fbeta   = (const float*)d_in[19];
    const float* W_fc      = (const float*)d_in[20];
    const float* b_fc      = (const float*)d_in[21];
    float* out = (float*)d_out;

    k_setup<<<1, 32>>>(lens, caps_in, out);
    k_pack<<<57888, 256>>>(W_ih, W_hh, W_fc, W_fbeta, W_dec_att, W_init_h, W_init_c);
    k_mean<<<dim3(4, BB), 128>>>(enc);
    k_gemm_init<<<dim3(8, 16), 256>>>();
    k_init_fin<<<64, 256>>>(b_init_h, b_init_c);
    k_small_fin<<<80, 256>>>(b_fc, out, 0);   // small(h0) only
    k_att1<<<dim3(49, 8), 128>>>(enc, W_enc_att, b_enc_att);

    for (int t = 0; t < TTT; ++t) {
        k_attn<<<BB, 256>>>(b_dec_att, W_full, b_full, out, t);
        k_stage<<<dim3(16, BB), 128>>>(enc, b_fbeta, t);
        k_gemm_gates_preds<<<700, 256>>>(emb, t);
        k_lstm<<<64, 256>>>(b_ih, b_hh, t);
        k_small_fin<<<1360, 256>>>(b_fc, out, t);   // small(t+1) + fin(t-1)
    }
    k_gemm_preds<<<316, 256>>>();
    k_fin_tail<<<dim3(40, BB), 256>>>(b_fc, out);
    (void)in_sizes; (void)n_in; (void)out_size;
}

// round 11
// speedup vs baseline: 1.2232x; 1.0576x over previous
#include <cuda_runtime.h>
#include <stdint.h>
#include <math.h>

#define BB 32
#define PP 196
#define EE 2048
#define AA 512
#define DD 512
#define MMM 512
#define VV 10000
#define LLL 20
#define TTT 19
#define KCC 3072
#define G4 2048
#define NBIG 12560 /* fbeta | dec_att | fc */

#define OFF_PRED  0
#define OFF_CAPS  (BB*TTT*VV)
#define OFF_ALPHA (OFF_CAPS + BB*LLL)
#define OFF_SORT  (OFF_ALPHA + BB*TTT*PP)

#define COL_GATE 0
#define COL_ATT2 2048
#define COL_FC   2560

#define NBLK 444   /* 148 SMs x 3 blocks — co-resident by construction */

typedef unsigned long long ull;
typedef unsigned int u32;

// -------- scratch --------
__device__ float g_att1[BB*PP*AA];
__device__ float g_wcomb[KCC*G4 + 2048];
__device__ float g_wic[EE*1024 + 2048];
__device__ float g_wbig[DD*NBIG + 4096];
__device__ float g_mean[BB*EE];
__device__ float g_h[BB*DD];
__device__ float g_c[BB*DD];
__device__ float g_alpha[BB*PP];
__device__ float g_x2[BB*2048];
__device__ float g_part[24*BB*G4];
__device__ float g_part2[4*BB*NBIG];
__device__ int   g_sortind[BB];
__device__ int   g_declen[BB];
__device__ int   g_caps[BB*LLL];
__device__ u32   g_bar_cnt;
__device__ u32   g_bar_gen;

__device__ __forceinline__ float sigm(float x) { return 1.0f / (1.0f + expf(-x)); }

__device__ __forceinline__ ull ffma2(ull a, ull b, ull c) {
    ull d;
    asm("fma.rn.f32x2 %0, %1, %2, %3;" : "=l"(d) : "l"(a), "l"(b), "l"(c));
    return d;
}
__device__ __forceinline__ float pairsum(ull v) {
    float2 f = *reinterpret_cast<float2*>(&v);
    return f.x + f.y;
}
__device__ __forceinline__ ull dup2(float a) {
    ull r;
    asm("mov.b64 %0, {%1, %1};" : "=l"(r) : "f"(a));
    return r;
}
__device__ __forceinline__ void cp_async16(u32 smem_addr, const void* gptr) {
    asm volatile("cp.async.cg.shared.global [%0], [%1], 16;" :: "r"(smem_addr), "l"(gptr));
}
__device__ __forceinline__ void cp_commit() {
    asm volatile("cp.async.commit_group;" ::: "memory");
}
template<int N> __device__ __forceinline__ void cp_wait() {
    asm volatile("cp.async.wait_group %0;" :: "n"(N) : "memory");
}

// -------- software grid barrier (all NBLK blocks co-resident) ---------------
__device__ __forceinline__ void grid_sync() {
    __syncthreads();
    if (threadIdx.x == 0) {
        u32 gen = *((volatile u32*)&g_bar_gen);
        __threadfence();
        u32 arr = atomicAdd(&g_bar_cnt, 1u);
        if (arr == NBLK - 1) {
            g_bar_cnt = 0;
            __threadfence();
            atomicAdd(&g_bar_gen, 1u);
        } else {
            while (*((volatile u32*)&g_bar_gen) == gen) { __nanosleep(64); }
            __threadfence();
        }
    }
    __syncthreads();
}

// ============ cp.async skinny-GEMM body (KSEG=128), row-pointer X loader =====
__device__ __forceinline__ void gemm4r(
    float* Xs, float* Ws, const float* const* rowp,
    const float* __restrict__ Wp, int N2,
    float* __restrict__ part, int npad, int N,
    int chunk, int seg, int colOffset)
{
    const int KSEG = 128;
    int tid = threadIdx.x;
    int cg = tid & 63, bg = tid >> 6;
    int colbase = colOffset + chunk * 128;
    int kb = seg * KSEG;

    __syncthreads();   // rowp ready; prior users of Xs/Ws done

    #pragma unroll
    for (int i = 0; i < 4; ++i) {
        int f = i * 256 + tid;
        int r = f >> 5;
        int c4 = (f & 31) * 4;
        *reinterpret_cast<float4*>(&Xs[r * KSEG + c4]) =
            *reinterpret_cast<const float4*>(rowp[r] + c4);
    }

    const float* wsrc = Wp + (size_t)(kb >> 1) * N2 + (size_t)colbase * 2;
    u32 wsm = (u32)__cvta_generic_to_shared(Ws);
    const int NSB = 8;

    auto issue = [&](int sb) {
        if (sb < NSB) {
            const float* src = wsrc + (size_t)sb * 8 * N2;
            u32 dst = wsm + (u32)((sb % 3) * 2048 * 4);
            #pragma unroll
            for (int i = 0; i < 2; ++i) {
                int f = i * 256 + tid;
                int r = f >> 6;
                int c = (f & 63) << 2;
                cp_async16(dst + (u32)(r * 256 + c) * 4, src + (size_t)r * N2 + c);
            }
        }
        cp_commit();
    };
    issue(0); issue(1);
    __syncthreads();

    int j0 = colbase + cg, j1 = j0 + 64;
    bool v0 = (j0 < N), v1 = (j1 < N);
    int b0 = bg * 8;

    ull acc0[8], acc1[8];
    #pragma unroll
    for (int i = 0; i < 8; ++i) { acc0[i] = 0ull; acc1[i] = 0ull; }

    for (int sb = 0; sb < NSB; ++sb) {
        cp_wait<1>();
        __syncthreads();
        const float* W0 = Ws + (sb % 3) * 2048;
        int kk = sb * 16;
        #pragma unroll
        for (int kp2 = 0; kp2 < 4; ++kp2) {
            ull wa0 = *reinterpret_cast<const ull*>(W0 + (kp2*2    ) * 256 + cg * 2);
            ull wa1 = *reinterpret_cast<const ull*>(W0 + (kp2*2 + 1) * 256 + cg * 2);
            ull wb0 = *reinterpret_cast<const ull*>(W0 + (kp2*2    ) * 256 + 128 + cg * 2);
            ull wb1 = *reinterpret_cast<const ull*>(W0 + (kp2*2 + 1) * 256 + 128 + cg * 2);
            #pragma unroll
            for (int i = 0; i < 8; ++i) {
                ulonglong2 xv = *reinterpret_cast<const ulonglong2*>(&Xs[(b0 + i) * KSEG + kk + kp2 * 4]);
                acc0[i] = ffma2(xv.x, wa0, acc0[i]);
                acc0[i] = ffma2(xv.y, wa1, acc0[i]);
                acc1[i] = ffma2(xv.x, wb0, acc1[i]);
                acc1[i] = ffma2(xv.y, wb1, acc1[i]);
            }
        }
        __syncthreads();
        issue(sb + 2);
    }

    float* pp = part + ((size_t)seg * 32 + b0) * npad;
    #pragma unroll
    for (int i = 0; i < 8; ++i) {
        if (v0) pp[(size_t)i * npad + j0] = pairsum(acc0[i]);
        if (v1) pp[(size_t)i * npad + j1] = pairsum(acc1[i]);
    }
}

// -------- setup --------
__global__ void k_setup(const int* __restrict__ lens, const int* __restrict__ caps_in,
                        float* __restrict__ out) {
    __shared__ int s_len[BB];
    __shared__ int s_si[BB];
    int tid = threadIdx.x;
    if (tid == 0) { g_bar_cnt = 0; g_bar_gen = 0; }
    if (tid < BB) s_len[tid] = lens[tid];
    __syncthreads();
    if (tid < BB) {
        int li = s_len[tid];
        int r = 0;
        for (int j = 0; j < BB; ++j) {
            int lj = s_len[j];
            if (lj > li || (lj == li && j < tid)) r++;
        }
        s_si[r] = tid;
    }
    __syncthreads();
    if (tid < BB) {
        int si = s_si[tid];
        g_sortind[tid] = si;
        g_declen[tid]  = s_len[si] - 1;
        out[OFF_SORT + tid] = (float)si;
    }
    __syncthreads();
    for (int i = tid; i < BB*LLL; i += blockDim.x) {
        int b = i / LLL, w = i % LLL;
        int cv = caps_in[s_si[b]*LLL + w];
        g_caps[i] = cv;
        out[OFF_CAPS + i] = (float)cv;
    }
}

// -------- one-time weight packing --------
__global__ void k_pack(const float* __restrict__ W_ih, const float* __restrict__ W_hh,
                       const float* __restrict__ W_fc, const float* __restrict__ W_fbeta,
                       const float* __restrict__ W_dec,
                       const float* __restrict__ Wih0, const float* __restrict__ Wic0) {
    const long long TA = (long long)KCC * G4;
    const long long TB = (long long)DD * NBIG;
    long long idx = (long long)blockIdx.x * 256 + threadIdx.x;
    if (idx < TA) {
        long long a = idx;
        int kp = (int)(a / (2*G4));
        int rem = (int)(a % (2*G4));
        int j = rem >> 1;
        int k = kp*2 + (rem & 1);
        float v = (k < 2560) ? W_ih[(size_t)j*2560 + k] : W_hh[(size_t)j*512 + (k - 2560)];
        g_wcomb[a] = v;
    } else if (idx < TA + TB) {
        long long b = idx - TA;
        int kp = (int)(b / (2*NBIG));
        int rem = (int)(b % (2*NBIG));
        int j = rem >> 1;
        int k = kp*2 + (rem & 1);
        float v;
        if (j < COL_ATT2)     v = W_fbeta[(size_t)k*EE + j];
        else if (j < COL_FC)  v = W_dec[(size_t)k*AA + (j - COL_ATT2)];
        else                  v = W_fc[(size_t)k*VV + (j - COL_FC)];
        g_wbig[b] = v;
    } else {
        long long c = idx - TA - TB;
        int kp = (int)(c >> 11);
        int rem = (int)(c & 2047);
        int j = rem >> 1;
        int k = kp*2 + (rem & 1);
        float v = (j < 512) ? Wih0[(size_t)k*512 + j] : Wic0[(size_t)k*512 + (j - 512)];
        g_wic[c] = v;
    }
}

// -------- mean over pixels --------
__global__ void k_mean(const float* __restrict__ enc) {
    int b = blockIdx.y;
    int j = (blockIdx.x * 128 + threadIdx.x) * 4;
    int sb = g_sortind[b];
    const float* base = enc + (size_t)sb * PP * EE + j;
    float4 s = make_float4(0.f, 0.f, 0.f, 0.f);
    #pragma unroll 4
    for (int p = 0; p < PP; ++p) {
        float4 v = *reinterpret_cast<const float4*>(base + (size_t)p * EE);
        s.x += v.x; s.y += v.y; s.z += v.z; s.w += v.w;
    }
    const float inv = 1.0f / 196.0f;
    s.x *= inv; s.y *= inv; s.z *= inv; s.w *= inv;
    *reinterpret_cast<float4*>(&g_mean[b*EE + j]) = s;
}

// -------- init GEMM: mean @ wic --------
__global__ __launch_bounds__(256, 3)
void k_gemm_init() {
    __shared__ __align__(16) float Xs[32*128];
    __shared__ __align__(16) float Ws[3*2048];
    __shared__ const float* rowp[32];
    int kb = blockIdx.y * 128;
    if (threadIdx.x < 32) rowp[threadIdx.x] = g_mean + threadIdx.x * EE + kb;
    gemm4r(Xs, Ws, rowp, g_wic, 2048, g_part, 1024, 1024,
           blockIdx.x, blockIdx.y, 0);
}

// -------- init epilogue --------
__global__ void k_init_fin(const float* __restrict__ b_init_h, const float* __restrict__ b_init_c) {
    int idx = blockIdx.x * blockDim.x + threadIdx.x;
    int b = idx >> 9, d = idx & 511;
    float h = b_init_h[d], c = b_init_c[d];
    #pragma unroll
    for (int s = 0; s < 16; ++s) {
        h += g_part[(s*32 + b)*1024 + d];
        c += g_part[(s*32 + b)*1024 + 512 + d];
    }
    g_h[idx] = h;
    g_c[idx] = c;
}

// -------- prologue small GEMM: h0 @ wbig[:, 0:2560) --------------------------
__global__ __launch_bounds__(256, 3)
void k_small0() {
    __shared__ __align__(16) float Xs[32*128];
    __shared__ __align__(16) float Ws[3*2048];
    __shared__ const float* rowp[32];
    int chunk = blockIdx.x % 20, seg = blockIdx.x / 20;
    if (threadIdx.x < 32) rowp[threadIdx.x] = g_h + threadIdx.x * DD + seg * 128;
    gemm4r(Xs, Ws, rowp, g_wbig, 2*NBIG, g_part2, NBIG, NBIG,
           chunk, seg, COL_GATE);
}

// -------- att1: [6272,2048]x[2048,512] f32x2 SGEMM, 128x64 tiles -------------
__global__ __launch_bounds__(128, 3)
void k_att1(const float* __restrict__ enc, const float* __restrict__ W,
            const float* __restrict__ bias) {
    __shared__ __align__(16) float As[16][128];
    __shared__ __align__(16) float Bs[16][64];
    int tid = threadIdx.x;
    int rowBase = blockIdx.x * 128;
    int colBase = blockIdx.y * 64;

    int grow = rowBase + tid;
    const float* asrc = enc + ((size_t)g_sortind[grow / PP] * PP + (grow % PP)) * EE;
    int bk0 = (tid >> 4) * 2;
    int bn  = (tid & 15) * 4;
    const float* bsrc = W + (size_t)bk0 * AA + colBase + bn;

    int m0 = (tid >> 3) * 8;
    int n0 = (tid & 7) * 8;

    ull acc[8][4];
    #pragma unroll
    for (int i = 0; i < 8; ++i)
        #pragma unroll
        for (int j = 0; j < 4; ++j) acc[i][j] = 0ull;

    float4 pa[4];
    #pragma unroll
    for (int u = 0; u < 4; ++u) pa[u] = *reinterpret_cast<const float4*>(asrc + 4*u);
    float4 pb0 = *reinterpret_cast<const float4*>(bsrc);
    float4 pb1 = *reinterpret_cast<const float4*>(bsrc + AA);

    for (int kb = 0; kb < EE; kb += 16) {
        #pragma unroll
        for (int u = 0; u < 4; ++u) {
            As[4*u + 0][tid] = pa[u].x;
            As[4*u + 1][tid] = pa[u].y;
            As[4*u + 2][tid] = pa[u].z;
            As[4*u + 3][tid] = pa[u].w;
        }
        *reinterpret_cast<float4*>(&Bs[bk0][bn])     = pb0;
        *reinterpret_cast<float4*>(&Bs[bk0 + 1][bn]) = pb1;
        __syncthreads();
        if (kb + 16 < EE) {
            #pragma unroll
            for (int u = 0; u < 4; ++u)
                pa[u] = *reinterpret_cast<const float4*>(asrc + kb + 16 + 4*u);
            pb0 = *reinterpret_cast<const float4*>(bsrc + (size_t)(kb + 16) * AA);
            pb1 = *reinterpret_cast<const float4*>(bsrc + (size_t)(kb + 17) * AA);
        }
        #pragma unroll
        for (int k = 0; k < 16; ++k) {
            float4 a0 = *reinterpret_cast<const float4*>(&As[k][m0]);
            float4 a1 = *reinterpret_cast<const float4*>(&As[k][m0 + 4]);
            ulonglong2 bp0 = *reinterpret_cast<const ulonglong2*>(&Bs[k][n0]);
            ulonglong2 bp1 = *reinterpret_cast<const ulonglong2*>(&Bs[k][n0 + 4]);
            float am[8] = {a0.x, a0.y, a0.z, a0.w, a1.x, a1.y, a1.z, a1.w};
            #pragma unroll
            for (int i = 0; i < 8; ++i) {
                ull ad = dup2(am[i]);
                acc[i][0] = ffma2(ad, bp0.x, acc[i][0]);
                acc[i][1] = ffma2(ad, bp0.y, acc[i][1]);
                acc[i][2] = ffma2(ad, bp1.x, acc[i][2]);
                acc[i][3] = ffma2(ad, bp1.y, acc[i][3]);
            }
        }
        __syncthreads();
    }
    float2 bb[4];
    #pragma unroll
    for (int jp = 0; jp < 4; ++jp)
        bb[jp] = *reinterpret_cast<const float2*>(bias + colBase + n0 + 2*jp);
    #pragma unroll
    for (int i = 0; i < 8; ++i) {
        int row = rowBase + m0 + i;
        #pragma unroll
        for (int jp = 0; jp < 4; ++jp) {
            float2 r = *reinterpret_cast<float2*>(&acc[i][jp]);
            float2 o = make_float2(r.x + bb[jp].x, r.y + bb[jp].y);
            *reinterpret_cast<float2*>(&g_att1[(size_t)row * AA + colBase + n0 + 2*jp]) = o;
        }
    }
}

// ================= persistent decode-loop kernel =============================
__global__ __launch_bounds__(256, 3)
void k_loop(const float* __restrict__ enc, const float* __restrict__ emb,
            const float* __restrict__ b_dec, const float* __restrict__ W_full,
            const float* __restrict__ b_full, const float* __restrict__ b_fbeta,
            const float* __restrict__ b_ih, const float* __restrict__ b_hh,
            const float* __restrict__ b_fc, float* __restrict__ out) {
    __shared__ __align__(16) float Xs[32*128];     // 16 KB
    __shared__ __align__(16) float Ws[3*2048];     // 24 KB
    __shared__ const float* rowp[32];
    __shared__ __align__(16) float att2s[AA];      // 2 KB
    __shared__ __align__(16) float wfs[AA];        // 2 KB
    __shared__ float es[256];
    __shared__ float red[256];
    __shared__ float al[200];

    int tid = threadIdx.x;
    int bx = blockIdx.x;

    for (int t = 0; t < TTT; ++t) {
        // ---- Phase A: attn(t) [32 units] -----------------------------------
        for (int unit = bx; unit < 32; unit += NBLK) {
            int b = unit;
            #pragma unroll
            for (int cc = 0; cc < 2; ++cc) {
                int c = tid + cc * 256;
                float a2 = b_dec[c];
                #pragma unroll
                for (int s = 0; s < 4; ++s)
                    a2 += g_part2[((size_t)s * 32 + b) * NBIG + COL_ATT2 + c];
                att2s[c] = a2;
                wfs[c] = W_full[c];
            }
            __syncthreads();
            int w = tid >> 5, lane = tid & 31;
            float bf = b_full[0];
            for (int p = w; p < PP; p += 8) {
                const float4* row4 = reinterpret_cast<const float4*>(g_att1 + ((size_t)b * PP + p) * AA);
                const float4* a24  = reinterpret_cast<const float4*>(att2s);
                const float4* wf4  = reinterpret_cast<const float4*>(wfs);
                float part = 0.0f;
                #pragma unroll
                for (int i = 0; i < 4; ++i) {
                    int a = lane + i * 32;
                    float4 v = row4[a];
                    float4 t2 = a24[a];
                    float4 wf = wf4[a];
                    part = fmaf(fmaxf(v.x + t2.x, 0.f), wf.x, part);
                    part = fmaf(fmaxf(v.y + t2.y, 0.f), wf.y, part);
                    part = fmaf(fmaxf(v.z + t2.z, 0.f), wf.z, part);
                    part = fmaf(fmaxf(v.w + t2.w, 0.f), wf.w, part);
                }
                #pragma unroll
                for (int off = 16; off; off >>= 1)
                    part += __shfl_down_sync(0xffffffffu, part, off);
                if (lane == 0) es[p] = part + bf;
            }
            __syncthreads();
            float v = (tid < PP) ? es[tid] : -1e30f;
            red[tid] = v; __syncthreads();
            for (int s = 128; s > 0; s >>= 1) { if (tid < s) red[tid] = fmaxf(red[tid], red[tid+s]); __syncthreads(); }
            float mx = red[0]; __syncthreads();
            float ex = (tid < PP) ? expf(v - mx) : 0.0f;
            red[tid] = ex; __syncthreads();
            for (int s = 128; s > 0; s >>= 1) { if (tid < s) red[tid] += red[tid+s]; __syncthreads(); }
            float inv = 1.0f / red[0];
            __syncthreads();
            if (tid < PP) {
                float alpha = ex * inv;
                g_alpha[b*PP + tid] = alpha;
                float m = (g_declen[b] > t) ? 1.0f : 0.0f;
                out[OFF_ALPHA + ((size_t)b*TTT + t)*PP + tid] = alpha * m;
            }
        }
        grid_sync();

        // ---- Phase B: stage — g_x2 = gate*awe (256 units of 256 j's) -------
        for (int unit = bx; unit < 256; unit += NBLK) {
            int b = unit >> 3;
            int j = (unit & 7) * 256 + tid;
            for (int i = tid; i < PP; i += 256) al[i] = g_alpha[b*PP + i];
            __syncthreads();
            int sb = g_sortind[b];
            const float* eb = enc + (size_t)sb * PP * EE + j;
            float awe0 = 0.f, awe1 = 0.f;
            #pragma unroll 8
            for (int p = 0; p < 192; p += 2) {
                awe0 = fmaf(al[p],     eb[(size_t)p * EE],       awe0);
                awe1 = fmaf(al[p + 1], eb[(size_t)(p + 1) * EE], awe1);
            }
            awe0 = fmaf(al[192], eb[(size_t)192 * EE], awe0);
            awe1 = fmaf(al[193], eb[(size_t)193 * EE], awe1);
            awe0 = fmaf(al[194], eb[(size_t)194 * EE], awe0);
            awe1 = fmaf(al[195], eb[(size_t)195 * EE], awe1);
            float awe = awe0 + awe1;
            float ga = b_fbeta[j];
            #pragma unroll
            for (int s = 0; s < 4; ++s)
                ga += g_part2[((size_t)s * 32 + b) * NBIG + COL_GATE + j];
            g_x2[b*2048 + j] = awe * sigm(ga);
            __syncthreads();
        }
        grid_sync();

        // ---- Phase C: gates(t) [384] + preds(t-1) [316] --------------------
        {
            int nC = 384 + (t > 0 ? 316 : 0);
            for (int unit = bx; unit < nC; unit += NBLK) {
                if (unit < 384) {
                    int chunk = unit & 15, seg = unit >> 4;
                    if (tid < 32) {
                        int kb = seg * 128;
                        const float* p;
                        if (seg < 4)       p = emb + (size_t)g_caps[tid*LLL + t] * MMM + kb;
                        else if (seg < 20) p = g_x2 + tid * 2048 + (kb - 512);
                        else               p = g_h + tid * DD + (kb - 2560);
                        rowp[tid] = p;
                    }
                    gemm4r(Xs, Ws, rowp, g_wcomb, 2*G4, g_part, G4, G4, chunk, seg, 0);
                } else {
                    int q = unit - 384;
                    int chunk = q % 79, seg = q / 79;
                    if (tid < 32) rowp[tid] = g_h + tid * DD + seg * 128;
                    gemm4r(Xs, Ws, rowp, g_wbig, 2*NBIG, g_part2, NBIG, NBIG,
                           chunk, seg, COL_FC);
                }
            }
        }
        grid_sync();

        // ---- Phase D: lstm(t) [units 0..63] + fin(t-1) [units 64..1343] ----
        {
            int nD = 64 + (t > 0 ? 1280 : 0);
            for (int unit = bx; unit < nD; unit += NBLK) {
                if (unit < 64) {
                    int idx = unit * 256 + tid;
                    int b = idx >> 9, d = idx & 511;
                    float s[4];
                    #pragma unroll
                    for (int g = 0; g < 4; ++g) {
                        float acc = b_ih[g*512 + d] + b_hh[g*512 + d];
                        #pragma unroll
                        for (int seg = 0; seg < 24; ++seg)
                            acc += g_part[((size_t)seg * 32 + b) * G4 + g*512 + d];
                        s[g] = acc;
                    }
                    float ig = sigm(s[0]), fg = sigm(s[1]), gg = tanhf(s[2]), og = sigm(s[3]);
                    float cn = fg * g_c[idx] + ig * gg;
                    float hn = og * tanhf(cn);
                    if (g_declen[b] > t) { g_h[idx] = hn; g_c[idx] = cn; }
                } else {
                    int q = unit - 64;
                    int b = q / 40;
                    int j = (q % 40) * 256 + tid;
                    int tprev = t - 1;
                    if (j < VV) {
                        float v = 0.0f;
                        if (g_declen[b] > tprev) {
                            v = b_fc[j];
                            #pragma unroll
                            for (int s = 0; s < 4; ++s)
                                v += g_part2[((size_t)s * 32 + b) * NBIG + COL_FC + j];
                        }
                        out[OFF_PRED + ((size_t)b*TTT + tprev)*VV + j] = v;
                    }
                }
            }
        }
        grid_sync();

        // ---- Phase E: small(t+1) [80 units] (skip after last step) ---------
        if (t < TTT - 1) {
            for (int unit = bx; unit < 80; unit += NBLK) {
                int chunk = unit % 20, seg = unit / 20;
                if (tid < 32) rowp[tid] = g_h + tid * DD + seg * 128;
                gemm4r(Xs, Ws, rowp, g_wbig, 2*NBIG, g_part2, NBIG, NBIG,
                       chunk, seg, COL_GATE);
            }
            grid_sync();
        }
    }

    // ---- Tail: preds(18) then fin(18) ---------------------------------------
    for (int unit = bx; unit < 316; unit += NBLK) {
        int chunk = unit % 79, seg = unit / 79;
        if (tid < 32) rowp[tid] = g_h + tid * DD + seg * 128;
        gemm4r(Xs, Ws, rowp, g_wbig, 2*NBIG, g_part2, NBIG, NBIG,
               chunk, seg, COL_FC);
    }
    grid_sync();
    for (int unit = bx; unit < 1280; unit += NBLK) {
        int b = unit / 40;
        int j = (unit % 40) * 256 + tid;
        if (j < VV) {
            float v = 0.0f;
            if (g_declen[b] > TTT - 1) {
                v = b_fc[j];
                #pragma unroll
                for (int s = 0; s < 4; ++s)
                    v += g_part2[((size_t)s * 32 + b) * NBIG + COL_FC + j];
            }
            out[OFF_PRED + ((size_t)b*TTT + (TTT-1))*VV + j] = v;
        }
    }
}

// ============================================================================
extern "C" void kernel_launch(void* const* d_in, const int* in_sizes, int n_in,
                              void* d_out, int out_size) {
    const float* enc       = (const float*)d_in[0];
    const int*   caps_in   = (const int*)  d_in[1];
    const int*   lens      = (const int*)  d_in[2];
    const float* W_enc_att = (const float*)d_in[3];
    const float* b_enc_att = (const float*)d_in[4];
    const float* W_dec_att = (const float*)d_in[5];
    const float* b_dec_att = (const float*)d_in[6];
    const float* W_full    = (const float*)d_in[7];
    const float* b_full    = (const float*)d_in[8];
    const float* emb       = (const float*)d_in[9];
    const float* W_ih      = (const float*)d_in[10];
    const float* W_hh      = (const float*)d_in[11];
    const float* b_ih      = (const float*)d_in[12];
    const float* b_hh      = (const float*)d_in[13];
    const float* W_init_h  = (const float*)d_in[14];
    const float* b_init_h  = (const float*)d_in[15];
    const float* W_init_c  = (const float*)d_in[16];
    const float* b_init_c  = (const float*)d_in[17];
    const float* W_fbeta   = (const float*)d_in[18];
    const float* b_fbeta   = (const float*)d_in[19];
    const float* W_fc      = (const float*)d_in[20];
    const float* b_fc      = (const float*)d_in[21];
    float* out = (float*)d_out;

    k_setup<<<1, 32>>>(lens, caps_in, out);
    k_pack<<<57888, 256>>>(W_ih, W_hh, W_fc, W_fbeta, W_dec_att, W_init_h, W_init_c);
    k_mean<<<dim3(4, BB), 128>>>(enc);
    k_gemm_init<<<dim3(8, 16), 256>>>();
    k_init_fin<<<64, 256>>>(b_init_h, b_init_c);
    k_small0<<<80, 256>>>();
    k_att1<<<dim3(49, 8), 128>>>(enc, W_enc_att, b_enc_att);

    k_loop<<<NBLK, 256>>>(enc, emb, b_dec_att, W_full, b_full, b_fbeta,
                          b_ih, b_hh, b_fc, out);
    (void)in_sizes; (void)n_in; (void)out_size;
}